// round 4
// baseline (speedup 1.0000x reference)
#include <cuda_runtime.h>
#include <cstdint>
#include <cstddef>

// Problem dims
#define BB 2
#define MM 4096
#define NN 4096
#define KK 4096
#define NT (KK / 128)          // 32 K-tiles of 128 bytes

// Packed sign operands (s8 in {+1,-1}); static scratch (no allocs allowed).
__device__ __align__(16) signed char g_xi8[(size_t)BB * MM * KK];
__device__ __align__(16) signed char g_yi8[(size_t)BB * NN * KK];

// ---------------------------------------------------------------------------
// Pack: fp32 -> s8 sign (+1 / -1)
// ---------------------------------------------------------------------------
__global__ void pack_signs(const float* __restrict__ in, signed char* __restrict__ out, int n4) {
    int i = blockIdx.x * blockDim.x + threadIdx.x;
    if (i >= n4) return;
    float4 v = reinterpret_cast<const float4*>(in)[i];
    char4 c;
    c.x = (__float_as_uint(v.x) >> 31) ? (signed char)-1 : (signed char)1;
    c.y = (__float_as_uint(v.y) >> 31) ? (signed char)-1 : (signed char)1;
    c.z = (__float_as_uint(v.z) >> 31) ? (signed char)-1 : (signed char)1;
    c.w = (__float_as_uint(v.w) >> 31) ? (signed char)-1 : (signed char)1;
    reinterpret_cast<char4*>(out)[i] = c;
}

// ---------------------------------------------------------------------------
// IMMA GEMM (mma.sync m16n8k32 s8), cp.async 3-stage pipeline.
// CTA tile 128x128, K-tile 128 bytes. 8 warps (2 M x 4 N), warp tile 64x32.
// smem per stage: A 128x128B (16KB) + B 128x128B (16KB), SW128 swizzled.
// ---------------------------------------------------------------------------
static constexpr int STAGES     = 3;
static constexpr int STAGE_SZ   = 32 * 1024;
static constexpr int SMEM_TOTAL = STAGES * STAGE_SZ;   // 98304

__device__ __forceinline__ void ldsm_x4(uint32_t addr, uint32_t& r0, uint32_t& r1,
                                        uint32_t& r2, uint32_t& r3) {
    asm volatile("ldmatrix.sync.aligned.m8n8.x4.shared.b16 {%0,%1,%2,%3}, [%4];"
                 : "=r"(r0), "=r"(r1), "=r"(r2), "=r"(r3) : "r"(addr));
}

__device__ __forceinline__ void mma_s8(int* c, const uint32_t* a, const uint32_t* b) {
    asm volatile(
        "mma.sync.aligned.m16n8k32.row.col.s32.s8.s8.s32 "
        "{%0,%1,%2,%3}, {%4,%5,%6,%7}, {%8,%9}, {%0,%1,%2,%3};"
        : "+r"(c[0]), "+r"(c[1]), "+r"(c[2]), "+r"(c[3])
        : "r"(a[0]), "r"(a[1]), "r"(a[2]), "r"(a[3]), "r"(b[0]), "r"(b[1]));
}

__device__ __forceinline__ void cp16(uint32_t dst, const void* src) {
    asm volatile("cp.async.cg.shared.global [%0], [%1], 16;" :: "r"(dst), "l"(src));
}

__global__ void __launch_bounds__(256, 2)
bingemm_imma(const float* __restrict__ xclip, const float* __restrict__ yclip,
             float* __restrict__ out) {
    extern __shared__ __align__(1024) char smem[];
    uint32_t sb;
    asm("{ .reg .u64 t; cvta.to.shared.u64 t, %1; cvt.u32.u64 %0, t; }" : "=r"(sb) : "l"(smem));

    const int tid  = threadIdx.x;
    const int lane = tid & 31;
    const int wid  = tid >> 5;
    const int wm   = wid >> 2;          // 0..1  (M warp)
    const int wn   = wid & 3;           // 0..3  (N warp)
    const int tn = blockIdx.x, tm = blockIdx.y, b = blockIdx.z;

    const signed char* Ab = g_xi8 + ((size_t)b * MM + (size_t)tm * 128) * KK;
    const signed char* Bb = g_yi8 + ((size_t)b * NN + (size_t)tn * 128) * KK;

    // per-thread cp.async coordinates: 1024 16B vectors per operand, 4 per thread
    const int ld_row0  = tid >> 1;              // rows tid/2 .. +? use idx scheme below
    (void)ld_row0;

    // ldmatrix per-lane coordinates
    const int rowA_l = (lane & 15);             // + wm*64 + mf*16
    const int hiA    = lane >> 4;               // k 16B-chunk select
    const int rowB_l = (lane & 7) + ((lane >> 4) << 3);   // + wn*32 + p*16
    const int hiB    = (lane >> 3) & 1;

    int acc[4][4][4];                            // [mf][nf][reg]
    #pragma unroll
    for (int i = 0; i < 4; i++)
        #pragma unroll
        for (int j = 0; j < 4; j++)
            #pragma unroll
            for (int r = 0; r < 4; r++) acc[i][j][r] = 0;

    // --- stage loader: 4 A-vectors + 4 B-vectors per thread ---
    auto load_stage = [&](int slot, int kt) {
        const uint32_t stA = sb + slot * STAGE_SZ;
        const uint32_t stB = stA + 16384;
        const int koff = kt * 128;
        #pragma unroll
        for (int i = 0; i < 4; i++) {
            int idx   = tid + i * 256;           // 0..1023
            int row   = idx >> 3;                // 0..127
            int chunk = idx & 7;
            uint32_t sw = (uint32_t)((chunk ^ (row & 7)) << 4);
            cp16(stA + row * 128 + sw, Ab + (size_t)row * KK + koff + chunk * 16);
            cp16(stB + row * 128 + sw, Bb + (size_t)row * KK + koff + chunk * 16);
        }
        asm volatile("cp.async.commit_group;" ::: "memory");
    };

    // prologue: stages 0,1
    load_stage(0, 0);
    load_stage(1, 1);

    for (int kt = 0; kt < NT; kt++) {
        asm volatile("cp.async.wait_group 1;" ::: "memory");
        __syncthreads();

        // issue next tile into slot (kt+2)%3 (read in iter kt-1; sync above fences it)
        if (kt + 2 < NT) load_stage((kt + 2) % STAGES, kt + 2);
        else asm volatile("cp.async.commit_group;" ::: "memory");

        const uint32_t stA = sb + (kt % STAGES) * STAGE_SZ;
        const uint32_t stB = stA + 16384;

        #pragma unroll
        for (int ks = 0; ks < 4; ks++) {
            uint32_t a[4][4];
            #pragma unroll
            for (int mf = 0; mf < 4; mf++) {
                int r = wm * 64 + mf * 16 + rowA_l;
                int c = (2 * ks + hiA) ^ (r & 7);
                ldsm_x4(stA + r * 128 + c * 16, a[mf][0], a[mf][1], a[mf][2], a[mf][3]);
            }
            uint32_t bfr[4][2];
            #pragma unroll
            for (int p = 0; p < 2; p++) {
                int r = wn * 32 + p * 16 + rowB_l;
                int c = (2 * ks + hiB) ^ (r & 7);
                ldsm_x4(stB + r * 128 + c * 16,
                        bfr[2 * p][0], bfr[2 * p][1], bfr[2 * p + 1][0], bfr[2 * p + 1][1]);
            }
            #pragma unroll
            for (int mf = 0; mf < 4; mf++)
                #pragma unroll
                for (int nf = 0; nf < 4; nf++)
                    mma_s8(acc[mf][nf], a[mf], bfr[nf]);
        }
        __syncthreads();   // all warps done reading slot before it's refilled
    }

    // --- epilogue: registers -> gmem, scaled ---
    const float scale = xclip[0] * yclip[0];
    const int mbase = tm * 128 + wm * 64 + (lane >> 2);
    const int nbase = tn * 128 + wn * 32 + (lane & 3) * 2;

    #pragma unroll
    for (int mf = 0; mf < 4; mf++) {
        #pragma unroll
        for (int nf = 0; nf < 4; nf++) {
            int m0 = mbase + mf * 16;
            int n0 = nbase + nf * 8;
            float2 v0, v1;
            v0.x = (float)acc[mf][nf][0] * scale;
            v0.y = (float)acc[mf][nf][1] * scale;
            v1.x = (float)acc[mf][nf][2] * scale;
            v1.y = (float)acc[mf][nf][3] * scale;
            *reinterpret_cast<float2*>(out + ((size_t)b * MM + m0) * NN + n0)       = v0;
            *reinterpret_cast<float2*>(out + ((size_t)b * MM + m0 + 8) * NN + n0)   = v1;
        }
    }
}

// ---------------------------------------------------------------------------
// Launch
// ---------------------------------------------------------------------------
extern "C" void kernel_launch(void* const* d_in, const int* in_sizes, int n_in,
                              void* d_out, int out_size) {
    const float* x     = (const float*)d_in[0];
    const float* y     = (const float*)d_in[1];
    const float* xclip = (const float*)d_in[2];
    const float* yclip = (const float*)d_in[3];
    float* out = (float*)d_out;

    signed char *xi8, *yi8;
    cudaGetSymbolAddress((void**)&xi8, g_xi8);
    cudaGetSymbolAddress((void**)&yi8, g_yi8);

    int n4x = in_sizes[0] / 4;
    int n4y = in_sizes[1] / 4;
    pack_signs<<<(n4x + 255) / 256, 256>>>(x, xi8, n4x);
    pack_signs<<<(n4y + 255) / 256, 256>>>(y, yi8, n4y);

    cudaFuncSetAttribute(bingemm_imma, cudaFuncAttributeMaxDynamicSharedMemorySize, SMEM_TOTAL);
    dim3 grid(NN / 128, MM / 128, BB);
    bingemm_imma<<<grid, 256, SMEM_TOTAL>>>(xclip, yclip, out);
}